// round 3
// baseline (speedup 1.0000x reference)
#include <cuda_runtime.h>
#include <cuda_bf16.h>
#include <cstdint>
#include <math.h>

#define BB 64      // batch
#define TT 256     // timesteps
#define UU 1024    // units
#define G3 3072    // 3*units
#define MROWS (BB * TT)

typedef __nv_bfloat16 bf16;

// ---------------------------------------------------------------------------
// Scratch (__device__ globals — the sanctioned no-alloc scratch path)
// ---------------------------------------------------------------------------
__device__ float g_xp[(size_t)MROWS * G3];     // projected inputs [t*64+b][3072]
__device__ float g_y1[(size_t)MROWS * UU];     // layer-1 outputs [t*64+b][1024]
__device__ bf16  g_ahi[(size_t)MROWS * UU];    // GEMM A hi
__device__ bf16  g_alo[(size_t)MROWS * UU];    // GEMM A lo
__device__ bf16  g_wthi[(size_t)G3 * UU];      // W^T (or U^T) hi  [3072][1024]
__device__ bf16  g_wtlo[(size_t)G3 * UU];      // W^T (or U^T) lo
__device__ bf16  g_hhi[2][BB * UU];            // h ping-pong, bf16 hi
__device__ bf16  g_hlo[2][BB * UU];            // h ping-pong, bf16 lo
__device__ float g_hf32[2][BB * UU];           // h ping-pong, fp32
__device__ float g_hzero[BB * UU];             // never written -> zeros

// ---------------------------------------------------------------------------
// PTX helpers (compute_100-safe: mma.sync / ldmatrix / cp.async only)
// ---------------------------------------------------------------------------
__device__ __forceinline__ uint32_t smem_u32(const void* p) {
    uint32_t a;
    asm("{ .reg .u64 t; cvta.to.shared.u64 t, %1; cvt.u32.u64 %0, t; }" : "=r"(a) : "l"(p));
    return a;
}
__device__ __forceinline__ void cp16(uint32_t dst, const void* src) {
    asm volatile("cp.async.cg.shared.global [%0], [%1], 16;" :: "r"(dst), "l"(src));
}
#define CP_COMMIT() asm volatile("cp.async.commit_group;")
#define CP_WAIT1()  asm volatile("cp.async.wait_group 1;")
#define CP_WAIT0()  asm volatile("cp.async.wait_group 0;")

__device__ __forceinline__ void ldsm4(uint32_t& r0, uint32_t& r1, uint32_t& r2,
                                      uint32_t& r3, uint32_t addr) {
    asm volatile("ldmatrix.sync.aligned.m8n8.x4.shared.b16 {%0,%1,%2,%3}, [%4];"
                 : "=r"(r0), "=r"(r1), "=r"(r2), "=r"(r3) : "r"(addr));
}
__device__ __forceinline__ void ldsm2(uint32_t& r0, uint32_t& r1, uint32_t addr) {
    asm volatile("ldmatrix.sync.aligned.m8n8.x2.shared.b16 {%0,%1}, [%2];"
                 : "=r"(r0), "=r"(r1) : "r"(addr));
}
__device__ __forceinline__ void mma16816(float* c, const uint32_t* a, const uint32_t* b) {
    asm volatile(
        "mma.sync.aligned.m16n8k16.row.col.f32.bf16.bf16.f32 "
        "{%0,%1,%2,%3}, {%4,%5,%6,%7}, {%8,%9}, {%0,%1,%2,%3};"
        : "+f"(c[0]), "+f"(c[1]), "+f"(c[2]), "+f"(c[3])
        : "r"(a[0]), "r"(a[1]), "r"(a[2]), "r"(a[3]), "r"(b[0]), "r"(b[1]));
}

// ---------------------------------------------------------------------------
// Converters
// ---------------------------------------------------------------------------
__global__ __launch_bounds__(256) void convert_x_kernel(const float* __restrict__ x) {
    // x [b][t][1024] -> g_ahi/g_alo rows ordered [t*64+b]
    for (size_t idx = (size_t)blockIdx.x * blockDim.x + threadIdx.x;
         idx < (size_t)MROWS * UU; idx += (size_t)gridDim.x * blockDim.x) {
        size_t r = idx >> 10, k = idx & 1023;
        size_t b = r & 63, t = r >> 6;
        float v = x[(((b << 8) + t) << 10) + k];
        bf16 hi = __float2bfloat16(v);
        g_ahi[idx] = hi;
        g_alo[idx] = __float2bfloat16(v - __bfloat162float(hi));
    }
}

__global__ __launch_bounds__(256) void convert_a_kernel(const float* __restrict__ src) {
    for (size_t idx = (size_t)blockIdx.x * blockDim.x + threadIdx.x;
         idx < (size_t)MROWS * UU; idx += (size_t)gridDim.x * blockDim.x) {
        float v = src[idx];
        bf16 hi = __float2bfloat16(v);
        g_ahi[idx] = hi;
        g_alo[idx] = __float2bfloat16(v - __bfloat162float(hi));
    }
}

__global__ void convert_w_kernel(const float* __restrict__ W) {
    // W [1024][3072] -> Wt hi/lo [3072][1024]
    __shared__ float tile[32][33];
    int tx = threadIdx.x, ty = threadIdx.y;           // 32 x 8
    int n = blockIdx.x * 32 + tx;
    int k = blockIdx.y * 32 + ty;
    #pragma unroll
    for (int j = 0; j < 32; j += 8)
        tile[ty + j][tx] = W[(size_t)(k + j) * G3 + n];
    __syncthreads();
    int k2 = blockIdx.y * 32 + tx;
    int n2 = blockIdx.x * 32 + ty;
    #pragma unroll
    for (int j = 0; j < 32; j += 8) {
        float v = tile[tx][ty + j];
        bf16 hi = __float2bfloat16(v);
        g_wthi[(size_t)(n2 + j) * UU + k2] = hi;
        g_wtlo[(size_t)(n2 + j) * UU + k2] = __float2bfloat16(v - __bfloat162float(hi));
    }
}

__global__ void convert_h_kernel(const float* __restrict__ h) {
    int idx = blockIdx.x * blockDim.x + threadIdx.x;
    if (idx < BB * UU) {
        float v = h[idx];
        bf16 hi = __float2bfloat16(v);
        g_hhi[0][idx] = hi;
        g_hlo[0][idx] = __float2bfloat16(v - __bfloat162float(hi));
    }
}

__global__ void zero_h_kernel() {
    int idx = blockIdx.x * blockDim.x + threadIdx.x;
    if (idx < BB * UU) {
        g_hhi[0][idx] = __float2bfloat16(0.0f);
        g_hlo[0][idx] = __float2bfloat16(0.0f);
    }
}

// ---------------------------------------------------------------------------
// Projection GEMM (mma.sync): C[16384][3072] = A @ Wt^T + bias
//   3-term bf16 split as K-concat: segs (ahi,wthi),(ahi,wtlo),(alo,wthi).
//   BM=BN=128, BK=32, 256 threads, warp tile 64x32, cp.async double buffer.
//   Smem rows padded to 80B (odd multiple of 16B -> ldmatrix conflict-free).
// ---------------------------------------------------------------------------
__global__ __launch_bounds__(256, 2) void proj_mma(const float* __restrict__ bias,
                                                   float* __restrict__ C) {
    __shared__ __align__(16) bf16 As[2][128 * 40];
    __shared__ __align__(16) bf16 Bs[2][128 * 40];

    const int tid = threadIdx.x, wid = tid >> 5, lane = tid & 31;
    const int m0 = blockIdx.y * 128, n0 = blockIdx.x * 128;
    const int mw = (wid >> 2) * 64, nw = (wid & 3) * 32;
    const uint32_t asb = smem_u32(As), bsb = smem_u32(Bs);

    const int lrow = tid >> 2;        // 0..63 (chunk row for i=0)
    const int lcc = tid & 3;          // 16B chunk within row

    float acc[4][4][4] = {};

    // -- loader: 2 A-chunks + 2 B-chunks per thread --
    auto load = [&](int it, int buf) {
        const int seg = it >> 5, kk = (it & 31) * 32;
        const bf16* Asrc = (seg < 2) ? g_ahi : g_alo;
        const bf16* Bsrc = (seg == 1) ? g_wtlo : g_wthi;
        #pragma unroll
        for (int i = 0; i < 2; i++) {
            const int row = lrow + i * 64;
            const uint32_t so = (uint32_t)buf * 10240u + (uint32_t)row * 80u +
                                (uint32_t)lcc * 16u;
            cp16(asb + so, Asrc + (size_t)(m0 + row) * UU + kk + lcc * 8);
            cp16(bsb + so, Bsrc + (size_t)(n0 + row) * UU + kk + lcc * 8);
        }
        CP_COMMIT();
    };

    load(0, 0);
    for (int it = 0; it < 96; it++) {
        const int buf = it & 1;
        if (it + 1 < 96) { load(it + 1, buf ^ 1); CP_WAIT1(); }
        else             { CP_WAIT0(); }
        __syncthreads();

        const uint32_t a_base = asb + (uint32_t)buf * 10240u;
        const uint32_t b_base = bsb + (uint32_t)buf * 10240u;
        #pragma unroll
        for (int ks = 0; ks < 2; ks++) {
            uint32_t af[4][4], bfr[4][2];
            #pragma unroll
            for (int mi = 0; mi < 4; mi++) {
                uint32_t addr = a_base +
                    (uint32_t)(mw + mi * 16 + (lane & 15)) * 80u +
                    (uint32_t)(ks * 16 + (lane >> 4) * 8) * 2u;
                ldsm4(af[mi][0], af[mi][1], af[mi][2], af[mi][3], addr);
            }
            #pragma unroll
            for (int p = 0; p < 2; p++) {
                uint32_t addr = b_base +
                    (uint32_t)(nw + p * 16 + (lane & 7) + (lane >> 4) * 8) * 80u +
                    (uint32_t)(ks * 16 + ((lane >> 3) & 1) * 8) * 2u;
                ldsm4(bfr[2 * p][0], bfr[2 * p][1], bfr[2 * p + 1][0], bfr[2 * p + 1][1], addr);
            }
            #pragma unroll
            for (int mi = 0; mi < 4; mi++)
                #pragma unroll
                for (int ni = 0; ni < 4; ni++)
                    mma16816(acc[mi][ni], af[mi], bfr[ni]);
        }
        __syncthreads();
    }

    // Epilogue: + bias, store fp32
    const int g = lane >> 2, t4 = lane & 3;
    #pragma unroll
    for (int mi = 0; mi < 4; mi++) {
        #pragma unroll
        for (int ni = 0; ni < 4; ni++) {
            const int row = m0 + mw + mi * 16 + g;
            const int col = n0 + nw + ni * 8 + t4 * 2;
            float2 bv = *(const float2*)(bias + col);
            float2 v0 = make_float2(acc[mi][ni][0] + bv.x, acc[mi][ni][1] + bv.y);
            float2 v1 = make_float2(acc[mi][ni][2] + bv.x, acc[mi][ni][3] + bv.y);
            *(float2*)&C[(size_t)row * G3 + col] = v0;
            *(float2*)&C[(size_t)(row + 8) * G3 + col] = v1;
        }
    }
}

// ---------------------------------------------------------------------------
// GRU step (mma.sync). grid 128 CTAs x 256 thr. CTA owns 8 j-cols x 3 gates.
// A (M=128): phase1 (K<1024) rows 0-63 = h_hi, 64-127 = h_lo vs U_hi;
//            phase2 (K>=1024) rows 0-63 = h_hi vs U_lo (warps 4-7 idle).
// C[128][24] -> smem reduce (rows m + m+64) -> GRU epilogue.
// U^T hi/lo live in g_wthi/g_wtlo (converted before the scan).
// ---------------------------------------------------------------------------
__global__ __launch_bounds__(256) void step_mma(
    const bf16* __restrict__ hhi, const bf16* __restrict__ hlo,
    const float* __restrict__ hf32_in, float* __restrict__ hf32_out,
    bf16* __restrict__ hhi_out, bf16* __restrict__ hlo_out,
    const float* __restrict__ brec, const float* __restrict__ xp_t,
    float* __restrict__ y_out, int y_stride)
{
    __shared__ __align__(16) bf16 As[2][128 * 40];
    __shared__ __align__(16) bf16 Bs[2][24 * 40];
    __shared__ float Cred[128][24];

    const int tid = threadIdx.x, wid = tid >> 5, lane = tid & 31;
    const int j0 = blockIdx.x * 8;
    const int wm = wid * 16;
    const uint32_t asb = smem_u32(As), bsb = smem_u32(Bs);

    float acc[3][4] = {};

    auto load = [&](int it, int buf) {
        const int k0 = it * 32;
        const bool ph2 = (k0 >= 1024);
        const int kk = ph2 ? k0 - 1024 : k0;
        const uint32_t abase = (uint32_t)buf * 10240u;
        if (!ph2) {
            #pragma unroll
            for (int i = 0; i < 2; i++) {
                const int row = (tid >> 2) + i * 64;
                const int cc = tid & 3;
                const bf16* src = (row < 64) ? (hhi + (size_t)row * UU)
                                             : (hlo + (size_t)(row - 64) * UU);
                cp16(asb + abase + (uint32_t)row * 80u + (uint32_t)cc * 16u,
                     src + kk + cc * 8);
            }
        } else {
            const int row = tid >> 2;        // 0..63
            const int cc = tid & 3;
            cp16(asb + abase + (uint32_t)row * 80u + (uint32_t)cc * 16u,
                 hhi + (size_t)row * UU + kk + cc * 8);
        }
        if (tid < 96) {
            const int row = tid >> 2, cc = tid & 3;   // 24 rows x 4 chunks
            const int gate = row >> 3, jj = row & 7;
            const bf16* Usrc = (ph2 ? g_wtlo : g_wthi) +
                (size_t)(gate * UU + j0 + jj) * UU + kk;
            cp16(bsb + (uint32_t)buf * 1920u + (uint32_t)row * 80u + (uint32_t)cc * 16u,
                 Usrc + cc * 8);
        }
        CP_COMMIT();
    };

    load(0, 0);
    for (int it = 0; it < 64; it++) {
        const int buf = it & 1;
        if (it + 1 < 64) { load(it + 1, buf ^ 1); CP_WAIT1(); }
        else             { CP_WAIT0(); }
        __syncthreads();

        const bool ph2 = (it >= 32);
        if (!(ph2 && wm >= 64)) {
            const uint32_t a_base = asb + (uint32_t)buf * 10240u;
            const uint32_t b_base = bsb + (uint32_t)buf * 1920u;
            #pragma unroll
            for (int ks = 0; ks < 2; ks++) {
                uint32_t af[4];
                ldsm4(af[0], af[1], af[2], af[3],
                      a_base + (uint32_t)(wm + (lane & 15)) * 80u +
                      (uint32_t)(ks * 16 + (lane >> 4) * 8) * 2u);
                uint32_t bq[4];
                ldsm4(bq[0], bq[1], bq[2], bq[3],
                      b_base + (uint32_t)((lane & 7) + (lane >> 4) * 8) * 80u +
                      (uint32_t)(ks * 16 + ((lane >> 3) & 1) * 8) * 2u);
                uint32_t b2[2];
                ldsm2(b2[0], b2[1],
                      b_base + (uint32_t)(16 + (lane & 7)) * 80u +
                      (uint32_t)(ks * 16 + ((lane >> 3) & 1) * 8) * 2u);
                mma16816(acc[0], af, bq + 0);
                mma16816(acc[1], af, bq + 2);
                mma16816(acc[2], af, b2);
            }
        }
        __syncthreads();
    }

    // Dump accumulators to smem
    const int g = lane >> 2, t4 = lane & 3;
    #pragma unroll
    for (int ni = 0; ni < 3; ni++) {
        Cred[wm + g][ni * 8 + t4 * 2]     = acc[ni][0];
        Cred[wm + g][ni * 8 + t4 * 2 + 1] = acc[ni][1];
        Cred[wm + g + 8][ni * 8 + t4 * 2]     = acc[ni][2];
        Cred[wm + g + 8][ni * 8 + t4 * 2 + 1] = acc[ni][3];
    }
    __syncthreads();

    // hi/lo reduce + GRU epilogue: 512 (m, jj) items, 2 per thread
    #pragma unroll
    for (int i = 0; i < 2; i++) {
        const int item = tid + i * 256;
        const int m = item >> 3, jj = item & 7;
        const int j = j0 + jj;
        const float rz = Cred[m][jj]       + Cred[m + 64][jj]       + brec[j];
        const float rr = Cred[m][8 + jj]   + Cred[m + 64][8 + jj]   + brec[UU + j];
        const float rh = Cred[m][16 + jj]  + Cred[m + 64][16 + jj]  + brec[2 * UU + j];
        const float xz = xp_t[(size_t)m * G3 + j];
        const float xr = xp_t[(size_t)m * G3 + UU + j];
        const float xh = xp_t[(size_t)m * G3 + 2 * UU + j];
        const float z = 1.0f / (1.0f + expf(-(xz + rz)));
        const float r = 1.0f / (1.0f + expf(-(xr + rr)));
        const float hh = tanhf(xh + r * rh);
        const float ho = hf32_in[(size_t)m * UU + j];
        const float hn = z * ho + (1.0f - z) * hh;
        hf32_out[(size_t)m * UU + j] = hn;
        y_out[(size_t)m * y_stride + j] = hn;
        bf16 hi = __float2bfloat16(hn);
        hhi_out[(size_t)m * UU + j] = hi;
        hlo_out[(size_t)m * UU + j] = __float2bfloat16(hn - __bfloat162float(hi));
    }
}

// ---------------------------------------------------------------------------
// kernel_launch
// ---------------------------------------------------------------------------
extern "C" void kernel_launch(void* const* d_in, const int* in_sizes, int n_in,
                              void* d_out, int out_size)
{
    const float* x      = (const float*)d_in[0];
    const float* hidden = (const float*)d_in[1];
    const float* W1     = (const float*)d_in[2];
    const float* U1     = (const float*)d_in[3];
    const float* b1     = (const float*)d_in[4];
    const float* W2     = (const float*)d_in[5];
    const float* U2     = (const float*)d_in[6];
    const float* b2     = (const float*)d_in[7];

    float* out   = (float*)d_out;
    float* state = out + (size_t)BB * TT * UU;

    float *xp, *y1, *hf32, *hz;
    bf16 *hhi, *hlo;
    cudaGetSymbolAddress((void**)&xp,   g_xp);
    cudaGetSymbolAddress((void**)&y1,   g_y1);
    cudaGetSymbolAddress((void**)&hhi,  g_hhi);
    cudaGetSymbolAddress((void**)&hlo,  g_hlo);
    cudaGetSymbolAddress((void**)&hf32, g_hf32);
    cudaGetSymbolAddress((void**)&hz,   g_hzero);

    const size_t HN = (size_t)BB * UU;
    dim3 pgrid(G3 / 128, MROWS / 128);   // (24, 128)
    dim3 wgrid(96, 32), wblk(32, 8);

    // ---- Layer 1 ----
    convert_w_kernel<<<wgrid, wblk>>>(W1);         // Wt1 -> g_wthi/lo
    convert_x_kernel<<<2048, 256>>>(x);
    proj_mma<<<pgrid, 256>>>(b1, xp);
    convert_w_kernel<<<wgrid, wblk>>>(U1);         // Ut1 -> g_wthi/lo (after proj1)
    convert_h_kernel<<<(BB * UU + 255) / 256, 256>>>(hidden);

    for (int t = 0; t < TT; t++) {
        const int in = t & 1, o = in ^ 1;
        const float* hin_f = (t == 0) ? hidden : hf32 + in * HN;
        step_mma<<<128, 256>>>(hhi + in * HN, hlo + in * HN,
                               hin_f, hf32 + o * HN,
                               hhi + o * HN, hlo + o * HN,
                               b1 + G3, xp + (size_t)t * BB * G3,
                               y1 + (size_t)t * BB * UU, UU);
    }

    // ---- Layer 2 ----
    convert_w_kernel<<<wgrid, wblk>>>(W2);
    convert_a_kernel<<<2048, 256>>>(y1);
    proj_mma<<<pgrid, 256>>>(b2, xp);
    convert_w_kernel<<<wgrid, wblk>>>(U2);
    zero_h_kernel<<<(BB * UU + 255) / 256, 256>>>();

    for (int t = 0; t < TT; t++) {
        const int in = t & 1, o = in ^ 1;
        const float* hin_f = (t == 0) ? hz : hf32 + in * HN;
        float* hout_f = (t == TT - 1) ? state : hf32 + o * HN;
        step_mma<<<128, 256>>>(hhi + in * HN, hlo + in * HN,
                               hin_f, hout_f,
                               hhi + o * HN, hlo + o * HN,
                               b2 + G3, xp + (size_t)t * BB * G3,
                               out + (size_t)t * UU, TT * UU);
    }
}

// round 5
// speedup vs baseline: 1.4750x; 1.4750x over previous
#include <cuda_runtime.h>
#include <cuda_bf16.h>
#include <cstdint>
#include <math.h>

#define BB 64      // batch
#define TT 256     // timesteps
#define UU 1024    // units
#define G3 3072    // 3*units
#define MROWS (BB * TT)

typedef __nv_bfloat16 bf16;

// ---------------------------------------------------------------------------
// Scratch (__device__ globals — sanctioned no-alloc scratch)
// ---------------------------------------------------------------------------
__device__ float g_xp[(size_t)MROWS * G3];     // projected inputs [t*64+b][3072]
__device__ bf16  g_ahi[(size_t)MROWS * UU];    // GEMM A hi (x, then y1)
__device__ bf16  g_alo[(size_t)MROWS * UU];    // GEMM A lo
__device__ bf16  g_wthi[(size_t)G3 * UU];      // W^T / U^T hi [3072][1024]
__device__ bf16  g_wtlo[(size_t)G3 * UU];      // W^T / U^T lo
__device__ bf16  g_hhi[2][BB * UU];            // h ping-pong bf16 hi
__device__ bf16  g_hlo[2][BB * UU];            // h ping-pong bf16 lo
__device__ float g_hf32[2][BB * UU];           // h ping-pong fp32
__device__ unsigned g_bar;                     // grid barrier counter

// ---------------------------------------------------------------------------
// PTX helpers (compute_100-safe: mma.sync / ldmatrix / cp.async only)
// ---------------------------------------------------------------------------
__device__ __forceinline__ uint32_t smem_u32(const void* p) {
    uint32_t a;
    asm("{ .reg .u64 t; cvta.to.shared.u64 t, %1; cvt.u32.u64 %0, t; }" : "=r"(a) : "l"(p));
    return a;
}
__device__ __forceinline__ void cp16(uint32_t dst, const void* src) {
    asm volatile("cp.async.cg.shared.global [%0], [%1], 16;" :: "r"(dst), "l"(src));
}
#define CP_COMMIT() asm volatile("cp.async.commit_group;")
#define CP_WAIT(n)  asm volatile("cp.async.wait_group %0;" :: "n"(n))

__device__ __forceinline__ void ldsm4(uint32_t& r0, uint32_t& r1, uint32_t& r2,
                                      uint32_t& r3, uint32_t addr) {
    asm volatile("ldmatrix.sync.aligned.m8n8.x4.shared.b16 {%0,%1,%2,%3}, [%4];"
                 : "=r"(r0), "=r"(r1), "=r"(r2), "=r"(r3) : "r"(addr));
}
__device__ __forceinline__ void mma16816(float* c, const uint32_t* a, const uint32_t* b) {
    asm volatile(
        "mma.sync.aligned.m16n8k16.row.col.f32.bf16.bf16.f32 "
        "{%0,%1,%2,%3}, {%4,%5,%6,%7}, {%8,%9}, {%0,%1,%2,%3};"
        : "+f"(c[0]), "+f"(c[1]), "+f"(c[2]), "+f"(c[3])
        : "r"(a[0]), "r"(a[1]), "r"(a[2]), "r"(a[3]), "r"(b[0]), "r"(b[1]));
}

// ---------------------------------------------------------------------------
// Converters
// ---------------------------------------------------------------------------
__global__ __launch_bounds__(256) void convert_x_kernel(const float* __restrict__ x) {
    for (size_t idx = (size_t)blockIdx.x * blockDim.x + threadIdx.x;
         idx < (size_t)MROWS * UU; idx += (size_t)gridDim.x * blockDim.x) {
        size_t r = idx >> 10, k = idx & 1023;
        size_t b = r & 63, t = r >> 6;
        float v = x[(((b << 8) + t) << 10) + k];
        bf16 hi = __float2bfloat16(v);
        g_ahi[idx] = hi;
        g_alo[idx] = __float2bfloat16(v - __bfloat162float(hi));
    }
}

__global__ void convert_w_kernel(const float* __restrict__ W) {
    __shared__ float tile[32][33];
    int tx = threadIdx.x, ty = threadIdx.y;           // 32 x 8
    int n = blockIdx.x * 32 + tx;
    int k = blockIdx.y * 32 + ty;
    #pragma unroll
    for (int j = 0; j < 32; j += 8)
        tile[ty + j][tx] = W[(size_t)(k + j) * G3 + n];
    __syncthreads();
    int k2 = blockIdx.y * 32 + tx;
    int n2 = blockIdx.x * 32 + ty;
    #pragma unroll
    for (int j = 0; j < 32; j += 8) {
        float v = tile[tx][ty + j];
        bf16 hi = __float2bfloat16(v);
        g_wthi[(size_t)(n2 + j) * UU + k2] = hi;
        g_wtlo[(size_t)(n2 + j) * UU + k2] = __float2bfloat16(v - __bfloat162float(hi));
    }
}

__global__ void convert_h_kernel(const float* __restrict__ h) {
    int idx = blockIdx.x * blockDim.x + threadIdx.x;
    if (idx < BB * UU) {
        float v = h[idx];
        bf16 hi = __float2bfloat16(v);
        g_hhi[0][idx] = hi;
        g_hlo[0][idx] = __float2bfloat16(v - __bfloat162float(hi));
        g_hf32[0][idx] = v;
    }
}

__global__ void zero_h_kernel() {
    int idx = blockIdx.x * blockDim.x + threadIdx.x;
    if (idx < BB * UU) {
        g_hhi[0][idx] = __float2bfloat16(0.0f);
        g_hlo[0][idx] = __float2bfloat16(0.0f);
        g_hf32[0][idx] = 0.0f;
    }
}

__global__ void reset_bar_kernel() { g_bar = 0u; }

// ---------------------------------------------------------------------------
// Projection GEMM (validated in round 3): C[16384][3072] = A @ Wt^T + bias
//   3-term bf16 split as K-concat; BM=BN=128, BK=32, 256 thr, 64x32 warp tile.
// ---------------------------------------------------------------------------
__global__ __launch_bounds__(256, 2) void proj_mma(const float* __restrict__ bias,
                                                   float* __restrict__ C) {
    __shared__ __align__(16) bf16 As[2][128 * 40];
    __shared__ __align__(16) bf16 Bs[2][128 * 40];

    const int tid = threadIdx.x, wid = tid >> 5, lane = tid & 31;
    const int m0 = blockIdx.y * 128, n0 = blockIdx.x * 128;
    const int mw = (wid >> 2) * 64, nw = (wid & 3) * 32;
    const uint32_t asb = smem_u32(As), bsb = smem_u32(Bs);
    const int lrow = tid >> 2, lcc = tid & 3;

    float acc[4][4][4] = {};

    auto load = [&](int it, int buf) {
        const int seg = it >> 5, kk = (it & 31) * 32;
        const bf16* Asrc = (seg < 2) ? g_ahi : g_alo;
        const bf16* Bsrc = (seg == 1) ? g_wtlo : g_wthi;
        #pragma unroll
        for (int i = 0; i < 2; i++) {
            const int row = lrow + i * 64;
            const uint32_t so = (uint32_t)buf * 10240u + (uint32_t)row * 80u +
                                (uint32_t)lcc * 16u;
            cp16(asb + so, Asrc + (size_t)(m0 + row) * UU + kk + lcc * 8);
            cp16(bsb + so, Bsrc + (size_t)(n0 + row) * UU + kk + lcc * 8);
        }
        CP_COMMIT();
    };

    load(0, 0);
    for (int it = 0; it < 96; it++) {
        const int buf = it & 1;
        if (it + 1 < 96) { load(it + 1, buf ^ 1); CP_WAIT(1); }
        else             { CP_WAIT(0); }
        __syncthreads();

        const uint32_t a_base = asb + (uint32_t)buf * 10240u;
        const uint32_t b_base = bsb + (uint32_t)buf * 10240u;
        #pragma unroll
        for (int ks = 0; ks < 2; ks++) {
            uint32_t af[4][4], bfr[4][2];
            #pragma unroll
            for (int mi = 0; mi < 4; mi++) {
                uint32_t addr = a_base +
                    (uint32_t)(mw + mi * 16 + (lane & 15)) * 80u +
                    (uint32_t)(ks * 16 + (lane >> 4) * 8) * 2u;
                ldsm4(af[mi][0], af[mi][1], af[mi][2], af[mi][3], addr);
            }
            #pragma unroll
            for (int p = 0; p < 2; p++) {
                uint32_t addr = b_base +
                    (uint32_t)(nw + p * 16 + (lane & 7) + (lane >> 4) * 8) * 80u +
                    (uint32_t)(ks * 16 + ((lane >> 3) & 1) * 8) * 2u;
                ldsm4(bfr[2 * p][0], bfr[2 * p][1], bfr[2 * p + 1][0], bfr[2 * p + 1][1], addr);
            }
            #pragma unroll
            for (int mi = 0; mi < 4; mi++)
                #pragma unroll
                for (int ni = 0; ni < 4; ni++)
                    mma16816(acc[mi][ni], af[mi], bfr[ni]);
        }
        __syncthreads();
    }

    const int g = lane >> 2, t4 = lane & 3;
    #pragma unroll
    for (int mi = 0; mi < 4; mi++) {
        #pragma unroll
        for (int ni = 0; ni < 4; ni++) {
            const int row = m0 + mw + mi * 16 + g;
            const int col = n0 + nw + ni * 8 + t4 * 2;
            float2 bv = *(const float2*)(bias + col);
            float2 v0 = make_float2(acc[mi][ni][0] + bv.x, acc[mi][ni][1] + bv.y);
            float2 v1 = make_float2(acc[mi][ni][2] + bv.x, acc[mi][ni][3] + bv.y);
            *(float2*)&C[(size_t)row * G3 + col] = v0;
            *(float2*)&C[(size_t)(row + 8) * G3 + col] = v1;
        }
    }
}

// ---------------------------------------------------------------------------
// Persistent GRU scan. grid=128 CTAs x 256 thr; CTA owns 8 j-cols.
// U^T slice (48 rows x 1024 K bf16: 24 hi + 24 lo) resident in SMEM.
// Per step: C[128][48] = [h_hi; h_lo] @ [U_hi | U_lo]; 4-quadrant sum =
// exact (hi+lo)*(hi+lo) recurrence product. Grid barrier between steps.
// SMEM map: U 0..99072 | A 4x10240 | Cred 128x48 f32 | bias 24 f32
// ---------------------------------------------------------------------------
#define US_PITCH 2064
#define AS_OFF   99072
#define A_BUF    10240
#define CRED_OFF (AS_OFF + 4 * A_BUF)            // 140032
#define BSM_OFF  (CRED_OFF + 128 * 48 * 4)       // 164608
#define SMEM_SCAN (BSM_OFF + 96)                 // 164704

template <int LAYER>
__global__ __launch_bounds__(256) void scan_mma(
    const float* __restrict__ brec,   // recurrent bias [3072]
    float* __restrict__ out_f32,      // LAYER 2: output base ([b][t][u])
    float* __restrict__ state)        // LAYER 2: final state
{
    extern __shared__ char smd[];
    float* Cred = (float*)(smd + CRED_OFF);
    float* bsm  = (float*)(smd + BSM_OFF);
    const uint32_t us_b = smem_u32(smd);
    const uint32_t as_b = us_b + AS_OFF;

    const int tid = threadIdx.x, wid = tid >> 5, lane = tid & 31;
    const int j0 = blockIdx.x * 8;

    // ---- One-time: load U^T slice (48 rows x 2048B) into smem ----
    #pragma unroll
    for (int i = 0; i < 24; i++) {
        const int ch = tid + i * 256;            // 0..6143
        const int row = ch >> 7, cc = ch & 127;
        const bf16* src;
        if (row < 24)
            src = g_wthi + ((size_t)((row >> 3) * UU + j0 + (row & 7))) * UU + cc * 8;
        else {
            const int rr = row - 24;
            src = g_wtlo + ((size_t)((rr >> 3) * UU + j0 + (rr & 7))) * UU + cc * 8;
        }
        cp16(us_b + (uint32_t)row * US_PITCH + (uint32_t)cc * 16u, src);
    }
    if (tid < 24) bsm[tid] = brec[(tid >> 3) * UU + j0 + (tid & 7)];
    CP_COMMIT();
    CP_WAIT(0);
    __syncthreads();

    const int arow = tid >> 2, acc4 = tid & 3;   // A-loader mapping

    for (int t = 0; t < TT; t++) {
        const int pin = t & 1, po = pin ^ 1;
        const bf16* hhi = g_hhi[pin];
        const bf16* hlo = g_hlo[pin];

        auto loadA = [&](int it, int buf) {
            const int k0 = it * 32;
            #pragma unroll
            for (int i = 0; i < 2; i++) {
                const int row = arow + i * 64;
                const bf16* src = (row < 64)
                    ? hhi + (size_t)row * UU + k0 + acc4 * 8
                    : hlo + (size_t)(row - 64) * UU + k0 + acc4 * 8;
                cp16(as_b + (uint32_t)buf * A_BUF + (uint32_t)row * 80u +
                     (uint32_t)acc4 * 16u, src);
            }
            CP_COMMIT();
        };

        float acc[6][4] = {};

        loadA(0, 0); loadA(1, 1); loadA(2, 2);
        for (int it = 0; it < 32; it++) {
            const int buf = it & 3;
            if (it + 3 < 32) { loadA(it + 3, (it + 3) & 3); CP_WAIT(3); }
            else if (it == 29) { CP_WAIT(2); }
            else if (it == 30) { CP_WAIT(1); }
            else if (it == 31) { CP_WAIT(0); }
            __syncthreads();

            const uint32_t a_base = as_b + (uint32_t)buf * A_BUF;
            #pragma unroll
            for (int ks = 0; ks < 2; ks++) {
                uint32_t af[4];
                ldsm4(af[0], af[1], af[2], af[3],
                      a_base + (uint32_t)(wid * 16 + (lane & 15)) * 80u +
                      (uint32_t)(ks * 16 + (lane >> 4) * 8) * 2u);
                uint32_t bfrag[6][2];
                const uint32_t kbyte =
                    ((uint32_t)(it * 32 + ks * 16) + ((lane >> 3) & 1) * 8u) * 2u;
                #pragma unroll
                for (int p = 0; p < 3; p++) {
                    ldsm4(bfrag[2 * p][0], bfrag[2 * p][1],
                          bfrag[2 * p + 1][0], bfrag[2 * p + 1][1],
                          us_b + (uint32_t)(p * 16 + (lane & 7) + (lane >> 4) * 8) *
                          US_PITCH + kbyte);
                }
                #pragma unroll
                for (int n = 0; n < 6; n++) mma16816(acc[n], af, bfrag[n]);
            }
            __syncthreads();
        }

        // Dump C to smem
        const int g = lane >> 2, t4 = lane & 3;
        #pragma unroll
        for (int n = 0; n < 6; n++) {
            Cred[(wid * 16 + g) * 48 + n * 8 + t4 * 2]     = acc[n][0];
            Cred[(wid * 16 + g) * 48 + n * 8 + t4 * 2 + 1] = acc[n][1];
            Cred[(wid * 16 + g + 8) * 48 + n * 8 + t4 * 2]     = acc[n][2];
            Cred[(wid * 16 + g + 8) * 48 + n * 8 + t4 * 2 + 1] = acc[n][3];
        }
        __syncthreads();

        // Epilogue: 512 (m, jj) items, 2 per thread
        #pragma unroll
        for (int i = 0; i < 2; i++) {
            const int item = tid + i * 256;
            const int m = item >> 3, jj = item & 7;
            const int j = j0 + jj;
            float rs[3];
            #pragma unroll
            for (int gt = 0; gt < 3; gt++) {
                const int c = gt * 8 + jj;
                rs[gt] = Cred[m * 48 + c] + Cred[(m + 64) * 48 + c] +
                         Cred[m * 48 + 24 + c] + Cred[(m + 64) * 48 + 24 + c] +
                         bsm[c];
            }
            const float* xb = g_xp + ((size_t)(t * 64 + m)) * G3;
            const float xz = xb[j], xr = xb[UU + j], xh = xb[2 * UU + j];
            const float z = 1.0f / (1.0f + expf(-(xz + rs[0])));
            const float r = 1.0f / (1.0f + expf(-(xr + rs[1])));
            const float hh = tanhf(xh + r * rs[2]);
            const float ho = g_hf32[pin][m * UU + j];
            const float hn = z * ho + (1.0f - z) * hh;
            g_hf32[po][m * UU + j] = hn;
            const bf16 hi = __float2bfloat16(hn);
            const bf16 lo = __float2bfloat16(hn - __bfloat162float(hi));
            g_hhi[po][m * UU + j] = hi;
            g_hlo[po][m * UU + j] = lo;
            if (LAYER == 1) {
                g_ahi[((size_t)(t * 64 + m)) * UU + j] = hi;
                g_alo[((size_t)(t * 64 + m)) * UU + j] = lo;
            } else {
                out_f32[(size_t)m * TT * UU + (size_t)t * UU + j] = hn;
                if (t == TT - 1) state[m * UU + j] = hn;
            }
        }

        // Grid barrier between steps (128 CTAs, all resident: 1 CTA/SM)
        if (t < TT - 1) {
            __threadfence();
            __syncthreads();
            if (tid == 0) {
                atomicAdd(&g_bar, 1u);
                const unsigned target = 128u * (unsigned)(t + 1);
                while (*(volatile unsigned*)&g_bar < target) __nanosleep(40);
                __threadfence();
            }
            __syncthreads();
        }
    }
}

// ---------------------------------------------------------------------------
// kernel_launch
// ---------------------------------------------------------------------------
extern "C" void kernel_launch(void* const* d_in, const int* in_sizes, int n_in,
                              void* d_out, int out_size)
{
    const float* x      = (const float*)d_in[0];
    const float* hidden = (const float*)d_in[1];
    const float* W1     = (const float*)d_in[2];
    const float* U1     = (const float*)d_in[3];
    const float* b1     = (const float*)d_in[4];
    const float* W2     = (const float*)d_in[5];
    const float* U2     = (const float*)d_in[6];
    const float* b2     = (const float*)d_in[7];

    float* out   = (float*)d_out;
    float* state = out + (size_t)BB * TT * UU;

    float* xp;
    cudaGetSymbolAddress((void**)&xp, g_xp);

    // Unconditional (no static guards per harness rules); non-stream API,
    // safe under graph capture.
    cudaFuncSetAttribute(scan_mma<1>, cudaFuncAttributeMaxDynamicSharedMemorySize, SMEM_SCAN);
    cudaFuncSetAttribute(scan_mma<2>, cudaFuncAttributeMaxDynamicSharedMemorySize, SMEM_SCAN);

    dim3 pgrid(G3 / 128, MROWS / 128);   // (24, 128)
    dim3 wgrid(96, 32), wblk(32, 8);

    // ---- Layer 1 ----
    convert_w_kernel<<<wgrid, wblk>>>(W1);
    convert_x_kernel<<<2048, 256>>>(x);
    proj_mma<<<pgrid, 256>>>(b1, xp);
    convert_w_kernel<<<wgrid, wblk>>>(U1);
    convert_h_kernel<<<(BB * UU + 255) / 256, 256>>>(hidden);
    reset_bar_kernel<<<1, 1>>>();
    scan_mma<1><<<128, 256, SMEM_SCAN>>>(b1 + G3, nullptr, nullptr);

    // ---- Layer 2 ----
    convert_w_kernel<<<wgrid, wblk>>>(W2);
    proj_mma<<<pgrid, 256>>>(b2, xp);      // input = y1 hi/lo written by scan 1
    convert_w_kernel<<<wgrid, wblk>>>(U2);
    zero_h_kernel<<<(BB * UU + 255) / 256, 256>>>();
    reset_bar_kernel<<<1, 1>>>();
    scan_mma<2><<<128, 256, SMEM_SCAN>>>(b2 + G3, out, state);
}